// round 3
// baseline (speedup 1.0000x reference)
#include <cuda_runtime.h>

#define N_NODES 1000
#define HIDDEN  256
#define IN_DIM  128
#define N_EDGES 64000

// Scratch (device globals: no allocation allowed)
__device__ float g_C[N_NODES * HIDDEN];    // A - B + b1   (per node)
__device__ float g_B[N_NODES * HIDDEN];    // B = X @ W1b^T (per node)
__device__ float g_H[N_NODES * HIDDEN];    // node features between layers
__device__ float g_W2T[HIDDEN * HIDDEN];   // W2 transposed (k-major)
__device__ int   g_src[N_EDGES];
__device__ int   g_dst[N_EDGES];
__device__ int   g_is64;

// ---------------------------------------------------------------------------
// Detect whether edge_index buffer is int64 (odd 32-bit words all zero) or int32.
__global__ void detect_idx(const unsigned int* __restrict__ w) {
    if (threadIdx.x == 0 && blockIdx.x == 0) {
        int is64 = 1;
        for (int i = 0; i < 128; i++)
            if (w[2 * i + 1] != 0u) { is64 = 0; break; }
        g_is64 = is64;
    }
}

// Materialize int32 src/dst arrays (clamped to valid range).
__global__ void convert_idx(const int* __restrict__ raw) {
    int e = blockIdx.x * blockDim.x + threadIdx.x;
    if (e >= N_EDGES) return;
    int s, d;
    if (g_is64) {
        s = raw[2 * e];
        d = raw[2 * (N_EDGES + e)];
    } else {
        s = raw[e];
        d = raw[N_EDGES + e];
    }
    g_src[e] = min(max(s, 0), N_NODES - 1);
    g_dst[e] = min(max(d, 0), N_NODES - 1);
}

// ---------------------------------------------------------------------------
// zero-fill (p == nullptr -> zero g_H)
__global__ void zero_kernel(float4* __restrict__ p, int n4) {
    float4* dst = p ? p : (float4*)g_H;
    int i = blockIdx.x * blockDim.x + threadIdx.x;
    if (i < n4) dst[i] = make_float4(0.f, 0.f, 0.f, 0.f);
}

// ---------------------------------------------------------------------------
// W2T[k][n] = W2[n][k]
__global__ void transpose_w2(const float* __restrict__ W) {
    __shared__ float t[32][33];
    int bx = blockIdx.x * 32;
    int by = blockIdx.y * 32;
#pragma unroll
    for (int i = 0; i < 32; i += 8)
        t[threadIdx.y + i][threadIdx.x] =
            W[(by + threadIdx.y + i) * HIDDEN + bx + threadIdx.x];
    __syncthreads();
#pragma unroll
    for (int i = 0; i < 32; i += 8)
        g_W2T[(bx + threadIdx.y + i) * HIDDEN + by + threadIdx.x] =
            t[threadIdx.x][threadIdx.y + i];
}

// ---------------------------------------------------------------------------
// Node GEMM: C[n][o] = sum_k H[n][k]*W1[o][k] - sum_k H[n][k]*W1[o][DIN+k] + b1[o]
//            B[n][o] = sum_k H[n][k]*W1[o][DIN+k]
// Hin == nullptr -> read g_H.  grid: (ceil(N/16), 2), block: 256
template <int DIN>
__global__ __launch_bounds__(256) void node_gemm(
    const float* __restrict__ Hin, const float* __restrict__ W1,
    const float* __restrict__ b1)
{
    const float* H = Hin ? Hin : g_H;
    __shared__ float Hs[16][DIN];
    const int tid = threadIdx.x;
    const int n_base = blockIdx.x * 16;

    const int nvec = 16 * DIN / 4;
    for (int i = tid; i < nvec; i += 256) {
        int row = i / (DIN / 4);
        int c4 = i % (DIN / 4);
        int n = n_base + row;
        float4 v = make_float4(0.f, 0.f, 0.f, 0.f);
        if (n < N_NODES) v = ((const float4*)(H + (size_t)n * DIN))[c4];
        ((float4*)&Hs[row][0])[c4] = v;
    }
    __syncthreads();

    const int o = blockIdx.y * 128 + (tid & 127);
    const int ng = tid >> 7;  // 0/1 -> node half

    float accA[8], accB[8];
#pragma unroll
    for (int j = 0; j < 8; j++) { accA[j] = 0.f; accB[j] = 0.f; }

    const float4* wA4 = (const float4*)(W1 + (size_t)o * 2 * DIN);
    const float4* wB4 = (const float4*)(W1 + (size_t)o * 2 * DIN + DIN);

    for (int k4 = 0; k4 < DIN / 4; k4++) {
        float4 wa = wA4[k4];
        float4 wb = wB4[k4];
        int kk = k4 * 4;
#pragma unroll
        for (int j = 0; j < 8; j++) {
            float h0 = Hs[ng * 8 + j][kk + 0];
            float h1 = Hs[ng * 8 + j][kk + 1];
            float h2 = Hs[ng * 8 + j][kk + 2];
            float h3 = Hs[ng * 8 + j][kk + 3];
            accA[j] += h0 * wa.x + h1 * wa.y + h2 * wa.z + h3 * wa.w;
            accB[j] += h0 * wb.x + h1 * wb.y + h2 * wb.z + h3 * wb.w;
        }
    }

    float bb = b1[o];
#pragma unroll
    for (int j = 0; j < 8; j++) {
        int n = n_base + ng * 8 + j;
        if (n < N_NODES) {
            g_B[n * HIDDEN + o] = accB[j];
            g_C[n * HIDDEN + o] = accA[j] - accB[j] + bb;
        }
    }
}

// ---------------------------------------------------------------------------
// Fused edge kernel: Z = relu(C[dst] + B[src]) ; P = Z @ W2T + b2 ;
// out[dst] = atomic max(out[dst], max(P, 0))  (out pre-zeroed; nonneg float
// atomicMax == int atomicMax).  outp == nullptr -> write g_H.
// grid: (E/128, 256/128), block: 256, 8x8 register microtiles
#define TM 128
#define TN 128
#define KT 16

__global__ __launch_bounds__(256, 2) void edge_kernel(
    const float* __restrict__ b2, float* __restrict__ outp)
{
    float* out = outp ? outp : g_H;
    __shared__ float Zs[KT][TM + 4];
    __shared__ float Ws[KT][TN];
    __shared__ int srcS[TM], dstS[TM];

    const int tid = threadIdx.x;
    const int e0 = blockIdx.x * TM;
    const int n_tile = blockIdx.y * TN;

    if (tid < TM) {
        srcS[tid] = g_src[e0 + tid];
        dstS[tid] = g_dst[e0 + tid];
    }
    __syncthreads();

    float acc[8][8];
#pragma unroll
    for (int i = 0; i < 8; i++)
#pragma unroll
        for (int j = 0; j < 8; j++) acc[i][j] = 0.f;

    const int tm = (tid & 15) * 8;
    const int tn = (tid >> 4) * 8;

    for (int kt = 0; kt < HIDDEN; kt += KT) {
        __syncthreads();
        // gather Z slab: 128 edges x 16 k  (512 float4 tasks, 2/thread)
#pragma unroll
        for (int i = 0; i < 2; i++) {
            int idx = tid + i * 256;
            int row = idx >> 2;
            int k4 = (idx & 3) * 4;
            const float4 c4 = *(const float4*)&g_C[dstS[row] * HIDDEN + kt + k4];
            const float4 b4 = *(const float4*)&g_B[srcS[row] * HIDDEN + kt + k4];
            Zs[k4 + 0][row] = fmaxf(c4.x + b4.x, 0.f);
            Zs[k4 + 1][row] = fmaxf(c4.y + b4.y, 0.f);
            Zs[k4 + 2][row] = fmaxf(c4.z + b4.z, 0.f);
            Zs[k4 + 3][row] = fmaxf(c4.w + b4.w, 0.f);
        }
        // W slab: Ws[k][n] = W2T[kt+k][n_tile+n]  (coalesced)
#pragma unroll
        for (int i = 0; i < 2; i++) {
            int id = tid + i * 256;
            int k = id >> 5;
            int c = (id & 31) * 4;
            *(float4*)&Ws[k][c] =
                *(const float4*)&g_W2T[(kt + k) * HIDDEN + n_tile + c];
        }
        __syncthreads();
#pragma unroll
        for (int k = 0; k < KT; k++) {
            float a[8], b[8];
            *(float4*)&a[0] = *(const float4*)&Zs[k][tm];
            *(float4*)&a[4] = *(const float4*)&Zs[k][tm + 4];
            *(float4*)&b[0] = *(const float4*)&Ws[k][tn];
            *(float4*)&b[4] = *(const float4*)&Ws[k][tn + 4];
#pragma unroll
            for (int i = 0; i < 8; i++)
#pragma unroll
                for (int j = 0; j < 8; j++)
                    acc[i][j] += a[i] * b[j];
        }
    }

    // epilogue: bias, clamp >=0, scatter-max via int atomicMax (nonneg floats)
    float bb[8];
#pragma unroll
    for (int j = 0; j < 8; j++) bb[j] = b2[n_tile + tn + j];

    int* oi = (int*)out;
#pragma unroll
    for (int i = 0; i < 8; i++) {
        int d = dstS[tm + i];
        int base = d * HIDDEN + n_tile + tn;
#pragma unroll
        for (int j = 0; j < 8; j++) {
            float v = acc[i][j] + bb[j];
            if (v > 0.f) atomicMax(&oi[base + j], __float_as_int(v));
        }
    }
}

// ---------------------------------------------------------------------------
extern "C" void kernel_launch(void* const* d_in, const int* in_sizes, int n_in,
                              void* d_out, int out_size) {
    const float* x = (const float*)d_in[0];
    const int* ei_raw = (const int*)d_in[1];

    detect_idx<<<1, 32>>>((const unsigned int*)ei_raw);
    convert_idx<<<(N_EDGES + 255) / 256, 256>>>(ei_raw);

    for (int l = 0; l < 5; l++) {
        const float* W1 = (const float*)d_in[2 + 4 * l];
        const float* b1 = (const float*)d_in[3 + 4 * l];
        const float* W2 = (const float*)d_in[4 + 4 * l];
        const float* b2 = (const float*)d_in[5 + 4 * l];

        if (l == 0)
            node_gemm<IN_DIM><<<dim3(63, 2), 256>>>(x, W1, b1);
        else
            node_gemm<HIDDEN><<<dim3(63, 2), 256>>>(nullptr, W1, b1);

        transpose_w2<<<dim3(8, 8), dim3(32, 8)>>>(W2);

        // last layer writes d_out, others write g_H (nullptr dispatch)
        float* outl = (l == 4) ? (float*)d_out : nullptr;
        zero_kernel<<<(N_NODES * HIDDEN / 4 + 255) / 256, 256>>>(
            (float4*)outl, N_NODES * HIDDEN / 4);

        edge_kernel<<<dim3(N_EDGES / TM, HIDDEN / TN), 256>>>(b2, outl);
    }
}

// round 5
// speedup vs baseline: 2.0377x; 2.0377x over previous
#include <cuda_runtime.h>
#include <cuda_bf16.h>
#include <cstdint>

#define N_NODES 1000
#define HIDDEN  256
#define IN_DIM  128
#define N_EDGES 64000

// Scratch (device globals: no allocation allowed)
__device__ float g_C[N_NODES * HIDDEN];    // A - B + b1   (per node)
__device__ float g_B[N_NODES * HIDDEN];    // B = X @ W1b^T (per node)
__device__ float g_H[N_NODES * HIDDEN];    // node features between layers
__device__ __nv_bfloat16 g_Whi[HIDDEN * HIDDEN];  // W2 hi (bf16, [n][k] k-major)
__device__ __nv_bfloat16 g_Wlo[HIDDEN * HIDDEN];  // W2 lo residual
__device__ int   g_src[N_EDGES];
__device__ int   g_dst[N_EDGES];
__device__ int   g_is64;

// ---------------------------------------------------------------------------
__device__ __forceinline__ uint32_t smem_u32(const void* p) {
    uint32_t a;
    asm("{ .reg .u64 t; cvta.to.shared.u64 t, %1; cvt.u32.u64 %0, t; }"
        : "=r"(a) : "l"(p));
    return a;
}

__device__ __forceinline__ void ldmatrix_x4(uint32_t* r, uint32_t addr) {
    asm volatile(
        "ldmatrix.sync.aligned.m8n8.x4.shared.b16 {%0, %1, %2, %3}, [%4];"
        : "=r"(r[0]), "=r"(r[1]), "=r"(r[2]), "=r"(r[3]) : "r"(addr));
}

__device__ __forceinline__ void mma_bf16(float* d, const uint32_t* a,
                                         const uint32_t* b) {
    asm volatile(
        "mma.sync.aligned.m16n8k16.row.col.f32.bf16.bf16.f32 "
        "{%0, %1, %2, %3}, {%4, %5, %6, %7}, {%8, %9}, {%0, %1, %2, %3};"
        : "+f"(d[0]), "+f"(d[1]), "+f"(d[2]), "+f"(d[3])
        : "r"(a[0]), "r"(a[1]), "r"(a[2]), "r"(a[3]), "r"(b[0]), "r"(b[1]));
}

// ---------------------------------------------------------------------------
// Edge-index dtype detection + int32 materialization (clamped)
__global__ void detect_idx(const unsigned int* __restrict__ w) {
    if (threadIdx.x == 0 && blockIdx.x == 0) {
        int is64 = 1;
        for (int i = 0; i < 128; i++)
            if (w[2 * i + 1] != 0u) { is64 = 0; break; }
        g_is64 = is64;
    }
}
__global__ void convert_idx(const int* __restrict__ raw) {
    int e = blockIdx.x * blockDim.x + threadIdx.x;
    if (e >= N_EDGES) return;
    int s, d;
    if (g_is64) { s = raw[2 * e]; d = raw[2 * (N_EDGES + e)]; }
    else        { s = raw[e];     d = raw[N_EDGES + e]; }
    g_src[e] = min(max(s, 0), N_NODES - 1);
    g_dst[e] = min(max(d, 0), N_NODES - 1);
}

// ---------------------------------------------------------------------------
// zero-fill (p == nullptr -> zero g_H)
__global__ void zero_kernel(float4* __restrict__ p, int n4) {
    float4* dst = p ? p : (float4*)g_H;
    int i = blockIdx.x * blockDim.x + threadIdx.x;
    if (i < n4) dst[i] = make_float4(0.f, 0.f, 0.f, 0.f);
}

// ---------------------------------------------------------------------------
// W2 fp32 -> (hi, lo) bf16 pair
__global__ void convert_w2(const float* __restrict__ W2) {
    int i = blockIdx.x * blockDim.x + threadIdx.x;
    if (i >= HIDDEN * HIDDEN) return;
    float w = W2[i];
    __nv_bfloat16 hi = __float2bfloat16(w);
    __nv_bfloat16 lo = __float2bfloat16(w - __bfloat162float(hi));
    g_Whi[i] = hi;
    g_Wlo[i] = lo;
}

// ---------------------------------------------------------------------------
// Node GEMM: C = A - B + b1, B = H @ W1b^T  (fp32, tiny: 1000x256)
template <int DIN>
__global__ __launch_bounds__(256) void node_gemm(
    const float* __restrict__ Hin, const float* __restrict__ W1,
    const float* __restrict__ b1)
{
    const float* H = Hin ? Hin : g_H;
    __shared__ float Hs[16][DIN];
    const int tid = threadIdx.x;
    const int n_base = blockIdx.x * 16;

    const int nvec = 16 * DIN / 4;
    for (int i = tid; i < nvec; i += 256) {
        int row = i / (DIN / 4);
        int c4 = i % (DIN / 4);
        int n = n_base + row;
        float4 v = make_float4(0.f, 0.f, 0.f, 0.f);
        if (n < N_NODES) v = ((const float4*)(H + (size_t)n * DIN))[c4];
        ((float4*)&Hs[row][0])[c4] = v;
    }
    __syncthreads();

    const int o = blockIdx.y * 128 + (tid & 127);
    const int ng = tid >> 7;

    float accA[8], accB[8];
#pragma unroll
    for (int j = 0; j < 8; j++) { accA[j] = 0.f; accB[j] = 0.f; }

    const float4* wA4 = (const float4*)(W1 + (size_t)o * 2 * DIN);
    const float4* wB4 = (const float4*)(W1 + (size_t)o * 2 * DIN + DIN);

    for (int k4 = 0; k4 < DIN / 4; k4++) {
        float4 wa = wA4[k4];
        float4 wb = wB4[k4];
        int kk = k4 * 4;
#pragma unroll
        for (int j = 0; j < 8; j++) {
            float h0 = Hs[ng * 8 + j][kk + 0];
            float h1 = Hs[ng * 8 + j][kk + 1];
            float h2 = Hs[ng * 8 + j][kk + 2];
            float h3 = Hs[ng * 8 + j][kk + 3];
            accA[j] += h0 * wa.x + h1 * wa.y + h2 * wa.z + h3 * wa.w;
            accB[j] += h0 * wb.x + h1 * wb.y + h2 * wb.z + h3 * wb.w;
        }
    }

    float bb = b1[o];
#pragma unroll
    for (int j = 0; j < 8; j++) {
        int n = n_base + ng * 8 + j;
        if (n < N_NODES) {
            g_B[n * HIDDEN + o] = accB[j];
            g_C[n * HIDDEN + o] = accA[j] - accB[j] + bb;
        }
    }
}

// ---------------------------------------------------------------------------
// HMMA fused edge kernel (split-bf16, mma.sync m16n8k16).
// Block tile: 64 edges x 128 cols, K=256 in chunks of 32.
// 8 warps = 2(m) x 4(n), warp tile 32x32.
// D = Zhi*Whi + Zhi*Wlo + Zlo*Whi  (fp32 frag accum).
// Epilogue: +bias, clamp>=0, int atomicMax scatter (out pre-zeroed).

#define TM 64
#define TN 128
#define TK 32
#define SK 40  // padded bf16 k-stride (80B rows: conflict-free ldmatrix)

__global__ __launch_bounds__(256, 2) void edge_hmma_kernel(
    const float* __restrict__ b2, float* __restrict__ outp)
{
    float* out = outp ? outp : g_H;
    __shared__ __align__(16) __nv_bfloat16 AsHi[TM * SK];
    __shared__ __align__(16) __nv_bfloat16 AsLo[TM * SK];
    __shared__ __align__(16) __nv_bfloat16 BsHi[TN * SK];
    __shared__ __align__(16) __nv_bfloat16 BsLo[TN * SK];
    __shared__ int dstS[TM], srcS[TM];

    const int tid = threadIdx.x;
    const int wid = tid >> 5;
    const int lane = tid & 31;
    const int e0 = blockIdx.x * TM;
    const int n0 = blockIdx.y * TN;

    if (tid < TM) {
        srcS[tid] = g_src[e0 + tid];
        dstS[tid] = g_dst[e0 + tid];
    }
    __syncthreads();

    const int wm = (wid >> 2) * 32;  // warp M offset
    const int wn = (wid & 3) * 32;   // warp N offset

    float acc[2][4][4];
#pragma unroll
    for (int i = 0; i < 2; i++)
#pragma unroll
        for (int j = 0; j < 4; j++)
#pragma unroll
            for (int r = 0; r < 4; r++) acc[i][j][r] = 0.f;

    // ldmatrix lane addresses (element offsets within tile, k-part added later)
    // A (m16xk16 quad): lanes 0-15 rows, lanes 16-31 rows with k+8
    const int a_row = lane & 15;
    const int a_kof = (lane >> 4) << 3;
    // B (two n8xk16): lanes 0-7 n0-7/k0, 8-15 n0-7/k8, 16-23 n8-15/k0, 24-31 n8-15/k8
    const int b_row = ((lane >> 4) << 3) + (lane & 7);
    const int b_kof = ((lane >> 3) & 1) << 3;

    for (int kt = 0; kt < HIDDEN; kt += TK) {
        __syncthreads();
        // ---- gather + split-convert Z: 64 rows x 32 k (512 float4 tasks) ----
#pragma unroll
        for (int i = 0; i < 2; i++) {
            int id = tid + i * 256;
            int row = id >> 3;
            int k4 = (id & 7) * 4;
            const float4 cz = *(const float4*)&g_C[dstS[row] * HIDDEN + kt + k4];
            const float4 bz = *(const float4*)&g_B[srcS[row] * HIDDEN + kt + k4];
            float z0 = fmaxf(cz.x + bz.x, 0.f);
            float z1 = fmaxf(cz.y + bz.y, 0.f);
            float z2 = fmaxf(cz.z + bz.z, 0.f);
            float z3 = fmaxf(cz.w + bz.w, 0.f);
            __nv_bfloat16 h0 = __float2bfloat16(z0), h1 = __float2bfloat16(z1);
            __nv_bfloat16 h2 = __float2bfloat16(z2), h3 = __float2bfloat16(z3);
            __nv_bfloat16 l0 = __float2bfloat16(z0 - __bfloat162float(h0));
            __nv_bfloat16 l1 = __float2bfloat16(z1 - __bfloat162float(h1));
            __nv_bfloat16 l2 = __float2bfloat16(z2 - __bfloat162float(h2));
            __nv_bfloat16 l3 = __float2bfloat16(z3 - __bfloat162float(h3));
            uint32_t hp0 = ((uint32_t)__bfloat16_as_ushort(h1) << 16) | __bfloat16_as_ushort(h0);
            uint32_t hp1 = ((uint32_t)__bfloat16_as_ushort(h3) << 16) | __bfloat16_as_ushort(h2);
            uint32_t lp0 = ((uint32_t)__bfloat16_as_ushort(l1) << 16) | __bfloat16_as_ushort(l0);
            uint32_t lp1 = ((uint32_t)__bfloat16_as_ushort(l3) << 16) | __bfloat16_as_ushort(l2);
            *(uint2*)&AsHi[row * SK + k4] = make_uint2(hp0, hp1);
            *(uint2*)&AsLo[row * SK + k4] = make_uint2(lp0, lp1);
        }
        // ---- load W slabs: 128 n-rows x 32 k (1024 uint2 tasks) ----
#pragma unroll
        for (int i = 0; i < 4; i++) {
            int id = tid + i * 256;
            int row = id >> 3;
            int k4 = (id & 7) * 4;
            *(uint2*)&BsHi[row * SK + k4] =
                *(const uint2*)&g_Whi[(n0 + row) * HIDDEN + kt + k4];
            *(uint2*)&BsLo[row * SK + k4] =
                *(const uint2*)&g_Wlo[(n0 + row) * HIDDEN + kt + k4];
        }
        __syncthreads();

        // ---- MMA: 2 k16 steps per chunk, 3 split passes ----
#pragma unroll
        for (int ks = 0; ks < TK; ks += 16) {
            uint32_t ahi[2][4], alo[2][4], bhi[2][4], blo[2][4];
#pragma unroll
            for (int mt = 0; mt < 2; mt++) {
                uint32_t addr = smem_u32(
                    &AsHi[(wm + mt * 16 + a_row) * SK + ks + a_kof]);
                ldmatrix_x4(ahi[mt], addr);
                addr = smem_u32(
                    &AsLo[(wm + mt * 16 + a_row) * SK + ks + a_kof]);
                ldmatrix_x4(alo[mt], addr);
            }
#pragma unroll
            for (int nt = 0; nt < 2; nt++) {
                uint32_t addr = smem_u32(
                    &BsHi[(wn + nt * 16 + b_row) * SK + ks + b_kof]);
                ldmatrix_x4(bhi[nt], addr);
                addr = smem_u32(
                    &BsLo[(wn + nt * 16 + b_row) * SK + ks + b_kof]);
                ldmatrix_x4(blo[nt], addr);
            }
#pragma unroll
            for (int mt = 0; mt < 2; mt++)
#pragma unroll
                for (int nt = 0; nt < 2; nt++) {
                    // bhi[nt] = {b0(n:0-7), b1(n:0-7), b0(n:8-15), b1(n:8-15)}
                    mma_bf16(acc[mt][nt * 2 + 0], ahi[mt], &bhi[nt][0]);
                    mma_bf16(acc[mt][nt * 2 + 1], ahi[mt], &bhi[nt][2]);
                    mma_bf16(acc[mt][nt * 2 + 0], ahi[mt], &blo[nt][0]);
                    mma_bf16(acc[mt][nt * 2 + 1], ahi[mt], &blo[nt][2]);
                    mma_bf16(acc[mt][nt * 2 + 0], alo[mt], &bhi[nt][0]);
                    mma_bf16(acc[mt][nt * 2 + 1], alo[mt], &bhi[nt][2]);
                }
        }
    }

    // ---- epilogue: bias, clamp, int atomicMax scatter ----
    int* oi = (int*)out;
    const int gr = lane >> 2;        // fragment row group
    const int gc = (lane & 3) * 2;   // fragment col base
#pragma unroll
    for (int mt = 0; mt < 2; mt++) {
#pragma unroll
        for (int half = 0; half < 2; half++) {
            int row = wm + mt * 16 + gr + half * 8;
            int d = dstS[row];
            int base = d * HIDDEN;
#pragma unroll
            for (int ns = 0; ns < 4; ns++) {
                int col = n0 + wn + ns * 8 + gc;
                float v0 = acc[mt][ns][half * 2 + 0] + b2[col];
                float v1 = acc[mt][ns][half * 2 + 1] + b2[col + 1];
                if (v0 > 0.f) atomicMax(&oi[base + col], __float_as_int(v0));
                if (v1 > 0.f) atomicMax(&oi[base + col + 1], __float_as_int(v1));
            }
        }
    }
}

// ---------------------------------------------------------------------------
extern "C" void kernel_launch(void* const* d_in, const int* in_sizes, int n_in,
                              void* d_out, int out_size) {
    const float* x = (const float*)d_in[0];
    const int* ei_raw = (const int*)d_in[1];

    detect_idx<<<1, 32>>>((const unsigned int*)ei_raw);
    convert_idx<<<(N_EDGES + 255) / 256, 256>>>(ei_raw);

    for (int l = 0; l < 5; l++) {
        const float* W1 = (const float*)d_in[2 + 4 * l];
        const float* b1 = (const float*)d_in[3 + 4 * l];
        const float* W2 = (const float*)d_in[4 + 4 * l];
        const float* b2 = (const float*)d_in[5 + 4 * l];

        if (l == 0)
            node_gemm<IN_DIM><<<dim3(63, 2), 256>>>(x, W1, b1);
        else
            node_gemm<HIDDEN><<<dim3(63, 2), 256>>>(nullptr, W1, b1);

        convert_w2<<<(HIDDEN * HIDDEN + 255) / 256, 256>>>(W2);

        float* outl = (l == 4) ? (float*)d_out : nullptr;
        zero_kernel<<<(N_NODES * HIDDEN / 4 + 255) / 256, 256>>>(
            (float4*)outl, N_NODES * HIDDEN / 4);

        edge_hmma_kernel<<<dim3(N_EDGES / TM, HIDDEN / TN), 256>>>(b2, outl);
    }
}

// round 6
// speedup vs baseline: 2.1637x; 1.0618x over previous
#include <cuda_runtime.h>
#include <cuda_bf16.h>
#include <cstdint>

#define N_NODES 1000
#define HIDDEN  256
#define IN_DIM  128
#define N_EDGES 64000

// Scratch (device globals: no allocation allowed)
__device__ float g_C[N_NODES * HIDDEN];    // A - B + b1   (per node)
__device__ float g_B[N_NODES * HIDDEN];    // B = X @ W1b^T (per node)
__device__ float g_H[N_NODES * HIDDEN];    // node features between layers
__device__ __nv_bfloat16 g_Whi[HIDDEN * HIDDEN];  // W2 hi (bf16, [n][k] k-major)
__device__ __nv_bfloat16 g_Wlo[HIDDEN * HIDDEN];  // W2 lo residual
__device__ int   g_src[N_EDGES];
__device__ int   g_dst[N_EDGES];
__device__ int   g_is64;

// ---------------------------------------------------------------------------
__device__ __forceinline__ uint32_t smem_u32(const void* p) {
    uint32_t a;
    asm("{ .reg .u64 t; cvta.to.shared.u64 t, %1; cvt.u32.u64 %0, t; }"
        : "=r"(a) : "l"(p));
    return a;
}
__device__ __forceinline__ void ldmatrix_x4(uint32_t* r, uint32_t addr) {
    asm volatile(
        "ldmatrix.sync.aligned.m8n8.x4.shared.b16 {%0, %1, %2, %3}, [%4];"
        : "=r"(r[0]), "=r"(r[1]), "=r"(r[2]), "=r"(r[3]) : "r"(addr));
}
__device__ __forceinline__ void mma_bf16(float* d, const uint32_t* a,
                                         const uint32_t* b) {
    asm volatile(
        "mma.sync.aligned.m16n8k16.row.col.f32.bf16.bf16.f32 "
        "{%0, %1, %2, %3}, {%4, %5, %6, %7}, {%8, %9}, {%0, %1, %2, %3};"
        : "+f"(d[0]), "+f"(d[1]), "+f"(d[2]), "+f"(d[3])
        : "r"(a[0]), "r"(a[1]), "r"(a[2]), "r"(a[3]), "r"(b[0]), "r"(b[1]));
}
__device__ __forceinline__ void cp_async16(uint32_t saddr, const void* gaddr) {
    asm volatile("cp.async.ca.shared.global [%0], [%1], 16;"
                 :: "r"(saddr), "l"(gaddr));
}
__device__ __forceinline__ void cp_commit() {
    asm volatile("cp.async.commit_group;");
}
__device__ __forceinline__ void cp_wait0() {
    asm volatile("cp.async.wait_group 0;");
}

// ---------------------------------------------------------------------------
// Edge-index dtype detection + int32 materialization (clamped)
__global__ void detect_idx(const unsigned int* __restrict__ w) {
    if (threadIdx.x == 0 && blockIdx.x == 0) {
        int is64 = 1;
        for (int i = 0; i < 128; i++)
            if (w[2 * i + 1] != 0u) { is64 = 0; break; }
        g_is64 = is64;
    }
}
__global__ void convert_idx(const int* __restrict__ raw) {
    int e = blockIdx.x * blockDim.x + threadIdx.x;
    if (e >= N_EDGES) return;
    int s, d;
    if (g_is64) { s = raw[2 * e]; d = raw[2 * (N_EDGES + e)]; }
    else        { s = raw[e];     d = raw[N_EDGES + e]; }
    g_src[e] = min(max(s, 0), N_NODES - 1);
    g_dst[e] = min(max(d, 0), N_NODES - 1);
}

// ---------------------------------------------------------------------------
// zero-fill (p == nullptr -> zero g_H)
__global__ void zero_kernel(float4* __restrict__ p, int n4) {
    float4* dst = p ? p : (float4*)g_H;
    int i = blockIdx.x * blockDim.x + threadIdx.x;
    if (i < n4) dst[i] = make_float4(0.f, 0.f, 0.f, 0.f);
}

// ---------------------------------------------------------------------------
// W2 fp32 -> (hi, lo) bf16 pair
__global__ void convert_w2(const float* __restrict__ W2) {
    int i = blockIdx.x * blockDim.x + threadIdx.x;
    if (i >= HIDDEN * HIDDEN) return;
    float w = W2[i];
    __nv_bfloat16 hi = __float2bfloat16(w);
    __nv_bfloat16 lo = __float2bfloat16(w - __bfloat162float(hi));
    g_Whi[i] = hi;
    g_Wlo[i] = lo;
}

// ---------------------------------------------------------------------------
// Node GEMM: C = A - B + b1, B = H @ W1b^T  (fp32, tiny: 1000x256)
template <int DIN>
__global__ __launch_bounds__(256) void node_gemm(
    const float* __restrict__ Hin, const float* __restrict__ W1,
    const float* __restrict__ b1)
{
    const float* H = Hin ? Hin : g_H;
    __shared__ float Hs[16][DIN];
    const int tid = threadIdx.x;
    const int n_base = blockIdx.x * 16;

    const int nvec = 16 * DIN / 4;
    for (int i = tid; i < nvec; i += 256) {
        int row = i / (DIN / 4);
        int c4 = i % (DIN / 4);
        int n = n_base + row;
        float4 v = make_float4(0.f, 0.f, 0.f, 0.f);
        if (n < N_NODES) v = ((const float4*)(H + (size_t)n * DIN))[c4];
        ((float4*)&Hs[row][0])[c4] = v;
    }
    __syncthreads();

    const int o = blockIdx.y * 128 + (tid & 127);
    const int ng = tid >> 7;

    float accA[8], accB[8];
#pragma unroll
    for (int j = 0; j < 8; j++) { accA[j] = 0.f; accB[j] = 0.f; }

    const float4* wA4 = (const float4*)(W1 + (size_t)o * 2 * DIN);
    const float4* wB4 = (const float4*)(W1 + (size_t)o * 2 * DIN + DIN);

    for (int k4 = 0; k4 < DIN / 4; k4++) {
        float4 wa = wA4[k4];
        float4 wb = wB4[k4];
        int kk = k4 * 4;
#pragma unroll
        for (int j = 0; j < 8; j++) {
            float h0 = Hs[ng * 8 + j][kk + 0];
            float h1 = Hs[ng * 8 + j][kk + 1];
            float h2 = Hs[ng * 8 + j][kk + 2];
            float h3 = Hs[ng * 8 + j][kk + 3];
            accA[j] += h0 * wa.x + h1 * wa.y + h2 * wa.z + h3 * wa.w;
            accB[j] += h0 * wb.x + h1 * wb.y + h2 * wb.z + h3 * wb.w;
        }
    }

    float bb = b1[o];
#pragma unroll
    for (int j = 0; j < 8; j++) {
        int n = n_base + ng * 8 + j;
        if (n < N_NODES) {
            g_B[n * HIDDEN + o] = accB[j];
            g_C[n * HIDDEN + o] = accA[j] - accB[j] + bb;
        }
    }
}

// ---------------------------------------------------------------------------
// HMMA fused edge kernel v2: TM=128 edges x TN=256 cols, 512 threads.
// Double-buffered K chunks of 32; W via cp.async; Z gather software-pipelined.
// 16 warps = 4(m) x 4(n); warp tile 32x64.
// D = Zhi*Whi + Zhi*Wlo + Zlo*Whi (fp32 frag accum).

#define TM 128
#define TN 256
#define TK 32
#define SK 40  // padded bf16 k-stride (80B rows: conflict-free ldmatrix)

// dynamic smem layout (bytes)
#define A_STAGE (TM * SK * 2)              // 10240
#define B_STAGE (TN * SK * 2)              // 20480
#define OFF_AHI 0
#define OFF_ALO (2 * A_STAGE)              // 20480
#define OFF_BHI (4 * A_STAGE)              // 40960
#define OFF_BLO (4 * A_STAGE + 2 * B_STAGE)// 81920
#define OFF_DST (4 * A_STAGE + 4 * B_STAGE)// 122880
#define OFF_SRC (OFF_DST + 512)
#define OFF_B2  (OFF_SRC + 512)
#define SM_TOTAL (OFF_B2 + 1024)           // 124928

__global__ __launch_bounds__(512, 1) void edge_hmma_kernel(
    const float* __restrict__ b2, float* __restrict__ outp)
{
    extern __shared__ char smem[];
    float* out = outp ? outp : g_H;
    const uint32_t sb = smem_u32(smem);
    const int tid = threadIdx.x;
    const int wid = tid >> 5;
    const int lane = tid & 31;
    const int e0 = blockIdx.x * TM;

    int* dstS = (int*)(smem + OFF_DST);
    int* srcS = (int*)(smem + OFF_SRC);
    float* b2s = (float*)(smem + OFF_B2);

    if (tid < TM) {
        srcS[tid] = g_src[e0 + tid];
        dstS[tid] = g_dst[e0 + tid];
    }
    if (tid < 256) b2s[tid] = b2[tid];
    __syncthreads();

    const int wm = (wid >> 2) * 32;  // warp M offset (0..96)
    const int wn = (wid & 3) * 64;   // warp N offset (0..192)

    float acc[2][8][4];
#pragma unroll
    for (int i = 0; i < 2; i++)
#pragma unroll
        for (int j = 0; j < 8; j++)
#pragma unroll
            for (int r = 0; r < 4; r++) acc[i][j][r] = 0.f;

    // ldmatrix lane addressing (same as validated R5 kernel)
    const int a_row = lane & 15;
    const int a_kof = (lane >> 4) << 3;
    const int b_row = ((lane >> 4) << 3) + (lane & 7);
    const int b_kof = ((lane >> 3) & 1) << 3;

    // ---- helpers as lambdas ----
    auto issue_W = [&](int buf, int kt) {
        // 2048 x 16B tasks (hi+lo) / 512 threads = 4 each
#pragma unroll
        for (int i = 0; i < 2; i++) {
            int id = tid + i * 512;               // 0..1023
            int row = id >> 2;                    // 0..255
            int k8 = (id & 3) * 8;                // 0,8,16,24
            uint32_t so = (uint32_t)(row * SK + k8) * 2;
            cp_async16(sb + OFF_BHI + buf * B_STAGE + so,
                       &g_Whi[row * HIDDEN + kt + k8]);
            cp_async16(sb + OFF_BLO + buf * B_STAGE + so,
                       &g_Wlo[row * HIDDEN + kt + k8]);
        }
        cp_commit();
    };
    auto ldg_Z = [&](int h, int kt, float4& cz, float4& bz) {
        int id = tid + h * 512;                   // 0..1023
        int row = id >> 3;                        // 0..127
        int k4 = (id & 7) * 4;                    // 0..28
        cz = *(const float4*)&g_C[dstS[row] * HIDDEN + kt + k4];
        bz = *(const float4*)&g_B[srcS[row] * HIDDEN + kt + k4];
    };
    auto sts_Z = [&](int h, int buf, const float4& cz, const float4& bz) {
        int id = tid + h * 512;
        int row = id >> 3;
        int k4 = (id & 7) * 4;
        float z0 = fmaxf(cz.x + bz.x, 0.f);
        float z1 = fmaxf(cz.y + bz.y, 0.f);
        float z2 = fmaxf(cz.z + bz.z, 0.f);
        float z3 = fmaxf(cz.w + bz.w, 0.f);
        __nv_bfloat16 h0 = __float2bfloat16(z0), h1 = __float2bfloat16(z1);
        __nv_bfloat16 h2 = __float2bfloat16(z2), h3 = __float2bfloat16(z3);
        __nv_bfloat16 l0 = __float2bfloat16(z0 - __bfloat162float(h0));
        __nv_bfloat16 l1 = __float2bfloat16(z1 - __bfloat162float(h1));
        __nv_bfloat16 l2 = __float2bfloat16(z2 - __bfloat162float(h2));
        __nv_bfloat16 l3 = __float2bfloat16(z3 - __bfloat162float(h3));
        uint32_t hp0 = ((uint32_t)__bfloat16_as_ushort(h1) << 16) | __bfloat16_as_ushort(h0);
        uint32_t hp1 = ((uint32_t)__bfloat16_as_ushort(h3) << 16) | __bfloat16_as_ushort(h2);
        uint32_t lp0 = ((uint32_t)__bfloat16_as_ushort(l1) << 16) | __bfloat16_as_ushort(l0);
        uint32_t lp1 = ((uint32_t)__bfloat16_as_ushort(l3) << 16) | __bfloat16_as_ushort(l2);
        uint32_t eo = (uint32_t)(row * SK + k4) * 2;
        *(uint2*)(smem + OFF_AHI + buf * A_STAGE + eo) = make_uint2(hp0, hp1);
        *(uint2*)(smem + OFF_ALO + buf * A_STAGE + eo) = make_uint2(lp0, lp1);
    };
    auto mma_ks = [&](int buf, int ks) {
        uint32_t ahi[2][4], alo[2][4];
#pragma unroll
        for (int mt = 0; mt < 2; mt++) {
            uint32_t ao = (uint32_t)((wm + mt * 16 + a_row) * SK + ks + a_kof) * 2;
            ldmatrix_x4(ahi[mt], sb + OFF_AHI + buf * A_STAGE + ao);
            ldmatrix_x4(alo[mt], sb + OFF_ALO + buf * A_STAGE + ao);
        }
#pragma unroll
        for (int nt = 0; nt < 4; nt++) {
            uint32_t bhi[4], blo[4];
            uint32_t bo = (uint32_t)((wn + nt * 16 + b_row) * SK + ks + b_kof) * 2;
            ldmatrix_x4(bhi, sb + OFF_BHI + buf * B_STAGE + bo);
            ldmatrix_x4(blo, sb + OFF_BLO + buf * B_STAGE + bo);
#pragma unroll
            for (int mt = 0; mt < 2; mt++) {
                mma_bf16(acc[mt][nt * 2 + 0], ahi[mt], &bhi[0]);
                mma_bf16(acc[mt][nt * 2 + 1], ahi[mt], &bhi[2]);
                mma_bf16(acc[mt][nt * 2 + 0], ahi[mt], &blo[0]);
                mma_bf16(acc[mt][nt * 2 + 1], ahi[mt], &blo[2]);
                mma_bf16(acc[mt][nt * 2 + 0], alo[mt], &bhi[0]);
                mma_bf16(acc[mt][nt * 2 + 1], alo[mt], &bhi[2]);
            }
        }
    };

    // ---- prologue: fill chunk 0 into buf 0 ----
    {
        issue_W(0, 0);
        float4 cz0, bz0, cz1, bz1;
        ldg_Z(0, 0, cz0, bz0);
        ldg_Z(1, 0, cz1, bz1);
        sts_Z(0, 0, cz0, bz0);
        sts_Z(1, 0, cz1, bz1);
        cp_wait0();
        __syncthreads();
    }

    // ---- main pipeline over 8 chunks ----
    for (int c = 0; c < 8; c++) {
        const int buf = c & 1;
        const int ktn = (c + 1) * TK;
        float4 cz0, bz0, cz1, bz1;
        if (c < 7) {
            issue_W(buf ^ 1, ktn);
            ldg_Z(0, ktn, cz0, bz0);   // LDGs in flight during ks=0 MMA
        }
        mma_ks(buf, 0);
        if (c < 7) {
            sts_Z(0, buf ^ 1, cz0, bz0);
            ldg_Z(1, ktn, cz1, bz1);   // in flight during ks=16 MMA
        }
        mma_ks(buf, 16);
        if (c < 7) {
            sts_Z(1, buf ^ 1, cz1, bz1);
            cp_wait0();
        }
        __syncthreads();
    }

    // ---- epilogue: bias, clamp, int atomicMax scatter ----
    int* oi = (int*)out;
    const int gr = lane >> 2;
    const int gc = (lane & 3) * 2;
#pragma unroll
    for (int mt = 0; mt < 2; mt++) {
#pragma unroll
        for (int half = 0; half < 2; half++) {
            int row = wm + mt * 16 + gr + half * 8;
            int d = dstS[row];
            int base = d * HIDDEN;
#pragma unroll
            for (int ns = 0; ns < 8; ns++) {
                int col = wn + ns * 8 + gc;
                float v0 = acc[mt][ns][half * 2 + 0] + b2s[col];
                float v1 = acc[mt][ns][half * 2 + 1] + b2s[col + 1];
                if (v0 > 0.f) atomicMax(&oi[base + col], __float_as_int(v0));
                if (v1 > 0.f) atomicMax(&oi[base + col + 1], __float_as_int(v1));
            }
        }
    }
}

// ---------------------------------------------------------------------------
extern "C" void kernel_launch(void* const* d_in, const int* in_sizes, int n_in,
                              void* d_out, int out_size) {
    const float* x = (const float*)d_in[0];
    const int* ei_raw = (const int*)d_in[1];

    static bool attr_set = false;
    if (!attr_set) {
        cudaFuncSetAttribute(edge_hmma_kernel,
                             cudaFuncAttributeMaxDynamicSharedMemorySize,
                             SM_TOTAL);
        attr_set = true;
    }

    detect_idx<<<1, 32>>>((const unsigned int*)ei_raw);
    convert_idx<<<(N_EDGES + 255) / 256, 256>>>(ei_raw);

    for (int l = 0; l < 5; l++) {
        const float* W1 = (const float*)d_in[2 + 4 * l];
        const float* b1 = (const float*)d_in[3 + 4 * l];
        const float* W2 = (const float*)d_in[4 + 4 * l];
        const float* b2 = (const float*)d_in[5 + 4 * l];

        if (l == 0)
            node_gemm<IN_DIM><<<dim3(63, 2), 256>>>(x, W1, b1);
        else
            node_gemm<HIDDEN><<<dim3(63, 2), 256>>>(nullptr, W1, b1);

        convert_w2<<<(HIDDEN * HIDDEN + 255) / 256, 256>>>(W2);

        float* outl = (l == 4) ? (float*)d_out : nullptr;
        zero_kernel<<<(N_NODES * HIDDEN / 4 + 255) / 256, 256>>>(
            (float4*)outl, N_NODES * HIDDEN / 4);

        edge_hmma_kernel<<<N_EDGES / TM, 512, SM_TOTAL>>>(b2, outl);
    }
}